// round 16
// baseline (speedup 1.0000x reference)
#include <cuda_runtime.h>
#include <cuda_bf16.h>
#include <math.h>
typedef unsigned long long ull;

constexpr int B=128,S=256,T=256,V=512,E=256,H=512,G=2048,H2=1024,EH2=1280;
constexpr int NB=128, NTP=512, NTG=256;

__device__ __align__(256) float g_xs[(size_t)2*S*B*E];
__device__ __align__(256) float g_edec[(size_t)T*B*E];
__device__ __align__(256) float g_pre[(size_t)2*S*B*G];
__device__ __align__(256) float g_preD[(size_t)T*B*G];
__device__ __align__(256) float g_y0[(size_t)2*S*B*H2];
__device__ __align__(256) __nv_bfloat16 g_encb[(size_t)S*B*H2];
__device__ __align__(256) float g_hb[2][2*B*H];
__device__ __align__(256) float g_cst[2*B*H];
__device__ __align__(256) float g_ctx[B*H2];
__device__ __align__(256) float g_d0hb[2][B*H];
__device__ __align__(256) float g_d1hb[2][B*H];
__device__ __align__(256) float g_h0i[B*H];
__device__ __align__(256) float g_c0i[B*H];
__device__ __align__(256) float g_h1i[B*H];
__device__ __align__(256) float g_c1i[B*H];
__device__ __align__(256) float g_partE[2][B*G];
__device__ __align__(256) float g_partQ[2][B*H2];
__device__ __align__(256) float g_partL[2][B*V];
__device__ __align__(256) float g_partW1[2][B*G];
__device__ __align__(256) float g_partC0[3][B*G];
__device__ __align__(256) float g_partC1[B*G];
__device__ __align__(256) float g_wE0ih[2*G*E];
__device__ __align__(256) float g_wE0hh[2*G*H];
__device__ __align__(256) float g_wE1ih[2*G*H2];
__device__ __align__(256) float g_wE1hh[2*G*H];
__device__ __align__(256) float g_wD0[G*EH2];
__device__ __align__(256) float g_wD0hh[G*H];
__device__ __align__(256) float g_wD1ih[G*H];
__device__ __align__(256) float g_wD1hh[G*H];
__device__ __align__(256) float g_be0[2*G];
__device__ __align__(256) float g_be1[2*G];
__device__ __align__(256) float g_bd0[G];
__device__ __align__(256) float g_bd1[G];

__device__ unsigned g_cnt, g_flag;

__device__ __forceinline__ void gbar(unsigned& phase)
{
    __syncthreads();
    if (threadIdx.x == 0) {
        __threadfence();
        const unsigned target = phase + 1;
        if (atomicAdd(&g_cnt, 1) == NB - 1) {
            g_cnt = 0; __threadfence();
            atomicExch(&g_flag, target);
        } else {
            while (*(volatile unsigned*)&g_flag < target) { __nanosleep(32); }
            __threadfence();
        }
        phase = target;
    }
    __syncthreads();
}

union UPair { ull u; float2 f; };
__device__ __forceinline__ ull dupf(float x){ ull r; asm("mov.b64 %0,{%1,%1};":"=l"(r):"f"(x)); return r; }
#define FMA2(d,a,b) asm("fma.rn.f32x2 %0,%1,%2,%0;":"+l"(d):"l"(a),"l"(b))
__device__ __forceinline__ float accf(ull a,int h){ UPair u; u.u=a; return h?u.f.y:u.f.x; }
__device__ __forceinline__ float sigf(float x){ return 1.f/(1.f+expf(-x)); }
__device__ __forceinline__ float2 bf2f(unsigned v){
    __nv_bfloat162 b=*reinterpret_cast<__nv_bfloat162*>(&v);
    return __bfloat1622float2(b);
}

// TM x 64 tile, 4x4 thread tile, NT=TM*4 threads. B-loader = first 256 threads.
template<int TM>
__device__ __forceinline__ void gcoreT(const float* __restrict__ A,int lda,
    const float* __restrict__ W,int ldw,int K,
    float (*As)[TM+4], float (*Bs)[68], ull acc[4][2])
{
    const int tid=threadIdx.x, tx=tid&15, ty=tid>>4;
    const int lr=tid>>2, lk=(tid&3)*4;
    const bool wact=(TM==64)||(tid<256);
    const float* ap=A+(size_t)lr*lda+lk;
    const float* wp=W+(size_t)lr*ldw+lk;
    float4 pa=__ldcg((const float4*)ap);
    float4 pw; if(wact) pw=*(const float4*)wp;
    int buf=0;
    #pragma unroll 1
    for(int kk=0;kk<K;kk+=16){
        const int b16=buf<<4;
        As[b16+lk+0][lr]=pa.x; As[b16+lk+1][lr]=pa.y;
        As[b16+lk+2][lr]=pa.z; As[b16+lk+3][lr]=pa.w;
        if(wact){
            Bs[b16+lk+0][lr]=pw.x; Bs[b16+lk+1][lr]=pw.y;
            Bs[b16+lk+2][lr]=pw.z; Bs[b16+lk+3][lr]=pw.w;
        }
        __syncthreads();
        if(kk+16<K){ pa=__ldcg((const float4*)(ap+kk+16)); if(wact) pw=*(const float4*)(wp+kk+16); }
        #pragma unroll
        for(int k=0;k<16;++k){
            const float4 a=*(const float4*)&As[b16+k][ty*4];
            const ull A0=dupf(a.x), A1=dupf(a.y), A2=dupf(a.z), A3=dupf(a.w);
            const ulonglong2 bv=*(const ulonglong2*)&Bs[b16+k][tx*4];
            FMA2(acc[0][0],A0,bv.x); FMA2(acc[0][1],A0,bv.y);
            FMA2(acc[1][0],A1,bv.x); FMA2(acc[1][1],A1,bv.y);
            FMA2(acc[2][0],A2,bv.x); FMA2(acc[2][1],A2,bv.y);
            FMA2(acc[3][0],A3,bv.x); FMA2(acc[3][1],A3,bv.y);
        }
        buf^=1;
    }
}

__device__ __forceinline__ void store_out(ull acc[4][2], float* __restrict__ C,
                                          int ldc, const float* __restrict__ bias)
{
    const int tid=threadIdx.x, tx=tid&15, ty=tid>>4;
    const float4 bv=*(const float4*)(bias+tx*4);
    #pragma unroll
    for(int r=0;r<4;++r){
        float4 o;
        o.x=accf(acc[r][0],0)+bv.x; o.y=accf(acc[r][0],1)+bv.y;
        o.z=accf(acc[r][1],0)+bv.z; o.w=accf(acc[r][1],1)+bv.w;
        *(float4*)(C+(size_t)(ty*4+r)*ldc+tx*4)=o;
    }
}
__device__ __forceinline__ void store_raw(ull acc[4][2], float* __restrict__ C, int ldc)
{
    const int tid=threadIdx.x, tx=tid&15, ty=tid>>4;
    #pragma unroll
    for(int r=0;r<4;++r){
        float4 o;
        o.x=accf(acc[r][0],0); o.y=accf(acc[r][0],1);
        o.z=accf(acc[r][1],0); o.w=accf(acc[r][1],1);
        *(float4*)(C+(size_t)(ty*4+r)*ldc+tx*4)=o;
    }
}

__global__ void prep_k(const int* __restrict__ src,const int* __restrict__ dec,
    const float* __restrict__ emb,
    const float* eWih0,const float* eWhh0,const float* ebih0,const float* ebhh0,
    const float* eWih1,const float* eWhh1,const float* ebih1,const float* ebhh1,
    const float* dWih0,const float* dWhh0,const float* dbih0,const float* dbhh0,
    const float* dWih1,const float* dWhh1,const float* dbih1,const float* dbhh1)
{
    const int id=blockIdx.x*blockDim.x+threadIdx.x;
    const int stride=gridDim.x*blockDim.x;
    for(int i=id;i<S*B*E;i+=stride){
        const int j=i%E, b=(i/E)%B, t=i/(E*B);
        const int tok=src[b*S+t];
        const float v=tok?emb[(size_t)tok*E+j]:0.f;
        g_xs[((size_t)t*B+b)*E+j]=v;
        g_xs[(size_t)S*B*E+((size_t)(S-1-t)*B+b)*E+j]=v;
    }
    for(int i=id;i<T*B*E;i+=stride){
        const int j=i%E, b=(i/E)%B, t=i/(E*B);
        const int tok=dec[b*T+t];
        g_edec[((size_t)t*B+b)*E+j]=tok?emb[(size_t)tok*E+j]:0.f;
    }
    auto P=[&](float* dst,const float* s2,int WID,int ZG){
        const int tot=ZG*G*WID;
        for(int i=id;i<tot;i+=stride){
            const int z=i/(G*WID), r=i-z*(G*WID), p=r/WID, k=r-p*WID;
            dst[i]=s2[((size_t)z*G+(p&3)*H+(p>>2))*WID+k];
        }
    };
    P(g_wE0ih,eWih0,E,2);  P(g_wE0hh,eWhh0,H,2);
    P(g_wE1ih,eWih1,H2,2); P(g_wE1hh,eWhh1,H,2);
    P(g_wD0,dWih0,EH2,1);  P(g_wD0hh,dWhh0,H,1);
    P(g_wD1ih,dWih1,H,1);  P(g_wD1hh,dWhh1,H,1);
    auto PB=[&](float* dst,const float* b0,const float* b1,int ZG){
        for(int i=id;i<ZG*G;i+=stride){
            const int z=i/G, p=i-z*G, o=(p&3)*H+(p>>2);
            dst[i]=b0[z*G+o]+b1[z*G+o];
        }
    };
    PB(g_be0,ebih0,ebhh0,2); PB(g_be1,ebih1,ebhh1,2);
    PB(g_bd0,dbih0,dbhh0,1); PB(g_bd1,dbih1,dbhh1,1);
}

__global__ __launch_bounds__(NTG,4) void gemm2_k(
    const float* __restrict__ A,int lda,int K,
    const float* __restrict__ W,int ldw,
    const float* __restrict__ bias,float* __restrict__ C,int ldc,
    long long zsA,long long zsW,long long zsB,long long zsC)
{
    __shared__ __align__(16) float As[32][68];
    __shared__ __align__(16) float Bs[32][68];
    const int z=blockIdx.z;
    ull acc[4][2]={{0,0},{0,0},{0,0},{0,0}};
    gcoreT<64>(A+z*zsA+(size_t)blockIdx.y*64*lda, lda,
               W+z*zsW+(size_t)blockIdx.x*64*ldw, ldw, K, As,Bs,acc);
    store_out(acc, C+z*zsC+(size_t)blockIdx.y*64*ldc+blockIdx.x*64, ldc,
              bias+z*zsB+blockIdx.x*64);
}

// encoder: cta = dir*64 + nt*2 + kh. kh=0 owns c + epilogue; kh=1 stores K-partial.
__global__ __launch_bounds__(NTP,1) void enc_layer_k(
    const float* __restrict__ pre, const float* __restrict__ whp,
    float* __restrict__ ynorm, float* __restrict__ yrev,
    __nv_bfloat16* __restrict__ encb,
    float* __restrict__ hsum, float* __restrict__ csum)
{
    __shared__ __align__(16) float As[32][132];
    __shared__ __align__(16) float Bs[32][68];
    const int cta=blockIdx.x, tid=threadIdx.x;
    unsigned ph=*(volatile unsigned*)&g_flag;
    for(int i=cta*NTP+tid;i<2*B*H;i+=NB*NTP) g_hb[0][i]=0.f;
    gbar(ph);
    const int dir=cta>>6, nt=(cta&63)>>1, kh=cta&1;
    const int tx=tid&15, ty=tid>>4;
    const int u=nt*16+tx;
    const float* Wt=whp+((size_t)dir*G+(size_t)nt*64)*H+kh*256;
    float c[4]={0.f,0.f,0.f,0.f};
    #pragma unroll 1
    for(int s=0;s<S;++s){
        const int par=s&1;
        ull acc[4][2]={{0,0},{0,0},{0,0},{0,0}};
        gcoreT<128>(g_hb[par]+(size_t)dir*B*H+kh*256, H, Wt, H, 256, As,Bs,acc);
        if(kh==1) store_raw(acc, g_partE[dir]+nt*64, G);
        gbar(ph);
        if(kh==0){
            const float* preT=pre+((size_t)dir*S+s)*B*G+nt*64;
            const float* parT=g_partE[dir]+nt*64;
            float* hout=g_hb[par^1]+(size_t)dir*B*H;
            const int tt=dir?(S-1-s):s;
            #pragma unroll
            for(int r=0;r<4;++r){
                const int b=ty*4+r;
                const float4 pv=__ldcg((const float4*)(preT+(size_t)b*G+tx*4));
                const float4 gv=__ldcg((const float4*)(parT+(size_t)b*G+tx*4));
                const float gi=accf(acc[r][0],0)+pv.x+gv.x;
                const float gf=accf(acc[r][0],1)+pv.y+gv.y;
                const float gg=accf(acc[r][1],0)+pv.z+gv.z;
                const float go=accf(acc[r][1],1)+pv.w+gv.w;
                const float cn=sigf(gf)*c[r]+sigf(gi)*tanhf(gg);
                c[r]=cn;
                const float hn=sigf(go)*tanhf(cn);
                hout[(size_t)b*H+u]=hn;
                if(ynorm) ynorm[((size_t)tt*B+b)*H2+dir*H+u]=hn;
                if(yrev)  yrev[((size_t)(S-1-tt)*B+b)*H2+dir*H+u]=hn;
                if(encb)  encb[((size_t)tt*B+b)*H2+dir*H+u]=__float2bfloat16(hn);
            }
        }
        gbar(ph);
    }
    if(kh==0){
        #pragma unroll
        for(int r=0;r<4;++r)
            g_cst[(size_t)dir*B*H+(size_t)(ty*4+r)*H+u]=c[r];
    }
    gbar(ph);
    for(int i=cta*NTP+tid;i<B*H;i+=NB*NTP){
        hsum[i]=__ldcg(&g_hb[0][i])+__ldcg(&g_hb[0][B*H+i]);
        csum[i]=__ldcg(&g_cst[i])+__ldcg(&g_cst[B*H+i]);
    }
}

__global__ __launch_bounds__(NTP,1) void dec_k(
    const float* __restrict__ pre, const int* __restrict__ src,
    const __nv_bfloat16* __restrict__ enc,
    const float* __restrict__ Wq, const float* __restrict__ bq,
    const float* __restrict__ Wout, const float* __restrict__ bout,
    float* __restrict__ out)
{
    __shared__ __align__(16) float As[32][132];
    __shared__ __align__(16) float Bs[32][68];
    __shared__ float qs[H2];
    __shared__ float sc[S];
    __shared__ float red[16];
    __shared__ float s_max, s_sum;
    const int cta=blockIdx.x, tid=threadIdx.x, lane=tid&31, w=tid>>5;
    const int tx=tid&15, ty=tid>>4;
    unsigned ph=*(volatile unsigned*)&g_flag;

    for(int i=cta*NTP+tid;i<B*H;i+=NB*NTP){
        g_d0hb[1][i]=g_h0i[i];
        g_d1hb[1][i]=g_h1i[i];
    }
    float c0r[4], c1r[4];
    if((cta&3)==0){
        const int j=cta>>2;
        #pragma unroll
        for(int r=0;r<4;++r) c0r[r]=g_c0i[(size_t)(ty*4+r)*H+j*16+tx];
    }
    if(cta<64 && !(cta&1)){
        const int i2=cta>>1;
        #pragma unroll
        for(int r=0;r<4;++r) c1r[r]=g_c1i[(size_t)(ty*4+r)*H+i2*16+tx];
    }
    gbar(ph);

    #pragma unroll 1
    for(int t=0;t<T;++t){
        const int par=t&1;
        const float* h1p=g_d1hb[par^1];

        // P1: q partials (0..31) | logits partials (32..47) | whh1 partials (64..127)
        if(cta<32){
            const int n=cta>>1, kh=cta&1;
            ull a1[4][2]={{0,0},{0,0},{0,0},{0,0}};
            gcoreT<128>(h1p+kh*256, H, Wq+(size_t)n*64*H+kh*256, H, 256, As,Bs,a1);
            store_raw(a1, g_partQ[kh]+n*64, H2);
        } else if(cta<48){
            if(t>0){
                const int m=(cta-32)>>1, kh=cta&1;
                ull a1[4][2]={{0,0},{0,0},{0,0},{0,0}};
                gcoreT<128>(h1p+kh*256, H, Wout+(size_t)m*64*H+kh*256, H, 256, As,Bs,a1);
                store_raw(a1, g_partL[kh]+m*64, V);
            }
        } else if(cta>=64){
            const int i2=(cta-64)>>1, kh=cta&1;
            ull a1[4][2]={{0,0},{0,0},{0,0},{0,0}};
            gcoreT<128>(h1p+kh*256, H, g_wD1hh+(size_t)i2*64*H+kh*256, H, 256, As,Bs,a1);
            store_raw(a1, g_partW1[kh]+i2*64, G);
        }
        gbar(ph);

        // P2: attention (CTA = batch)
        {
            const int b=cta;
            for(int k=tid;k<H2;k+=NTP)
                qs[k]=__ldcg(g_partQ[0]+(size_t)b*H2+k)+__ldcg(g_partQ[1]+(size_t)b*H2+k)+bq[k];
            __syncthreads();
            for(int s=w;s<S;s+=16){
                const __nv_bfloat16* eb=enc+((size_t)s*B+b)*H2;
                float sum=0.f;
                #pragma unroll
                for(int k=lane*8;k<H2;k+=256){
                    const uint4 ev=*(const uint4*)(eb+k);
                    const float2 f0=bf2f(ev.x), f1=bf2f(ev.y);
                    const float2 f2=bf2f(ev.z), f3=bf2f(ev.w);
                    sum+=f0.x*qs[k]+f0.y*qs[k+1]+f1.x*qs[k+2]+f1.y*qs[k+3]
                        +f2.x*qs[k+4]+f2.y*qs[k+5]+f3.x*qs[k+6]+f3.y*qs[k+7];
                }
                #pragma unroll
                for(int o=16;o;o>>=1) sum+=__shfl_xor_sync(0xffffffffu,sum,o);
                if(lane==0) sc[s]=(src[b*S+s]!=0)?sum:-1e9f;
            }
            __syncthreads();
            const float v=(tid<S)?sc[tid]:-3.0e38f;
            float m=v;
            #pragma unroll
            for(int o=16;o;o>>=1) m=fmaxf(m,__shfl_xor_sync(0xffffffffu,m,o));
            if(lane==0) red[w]=m;
            __syncthreads();
            if(tid==0){
                float mm=red[0];
                #pragma unroll
                for(int i=1;i<16;++i) mm=fmaxf(mm,red[i]);
                s_max=mm;
            }
            __syncthreads();
            const float ev=(tid<S)?expf(v-s_max):0.f;
            float sum=ev;
            #pragma unroll
            for(int o=16;o;o>>=1) sum+=__shfl_xor_sync(0xffffffffu,sum,o);
            if(lane==0) red[w]=sum;
            __syncthreads();
            if(tid==0){
                float ss=0.f;
                #pragma unroll
                for(int i=0;i<16;++i) ss+=red[i];
                s_sum=ss;
            }
            __syncthreads();
            if(tid<S) sc[tid]=ev/s_sum;
            __syncthreads();
            const int k2=tid*2;
            float a0=0.f, a1=0.f;
            const __nv_bfloat16* ep=enc+(size_t)b*H2+k2;
            #pragma unroll 8
            for(int s=0;s<S;++s){
                const float p=sc[s];
                const float2 f=bf2f(*(const unsigned*)(ep+(size_t)s*B*H2));
                a0+=p*f.x; a1+=p*f.y;
            }
            float2 o2; o2.x=a0; o2.y=a1;
            *(float2*)(g_ctx+(size_t)b*H2+k2)=o2;
        }
        gbar(ph);

        // P3: cell0 4-way K split per N-tile j (cta=4j+q4); slice0 owner keeps regs
        ull acc3[4][2]={{0,0},{0,0},{0,0},{0,0}};
        {
            const int j=cta>>2, q4=cta&3;
            const float* Wj=g_wD0+E+(size_t)j*64*EH2;
            if(q4==0){
                gcoreT<128>(g_ctx, H2, Wj, EH2, 384, As,Bs,acc3);
            } else if(q4==1){
                gcoreT<128>(g_ctx+384, H2, Wj+384, EH2, 384, As,Bs,acc3);
                store_raw(acc3, g_partC0[0]+j*64, G);
            } else if(q4==2){
                gcoreT<128>(g_ctx+768, H2, Wj+768, EH2, 256, As,Bs,acc3);
                gcoreT<128>(g_d0hb[par^1], H, g_wD0hh+(size_t)j*64*H, H, 128, As,Bs,acc3);
                store_raw(acc3, g_partC0[1]+j*64, G);
            } else {
                gcoreT<128>(g_d0hb[par^1]+128, H, g_wD0hh+128+(size_t)j*64*H, H, 384, As,Bs,acc3);
                store_raw(acc3, g_partC0[2]+j*64, G);
            }
        }
        gbar(ph);

        // P4: cell0 epilogue (cta%4==0) | logits finalize (cta%4==1, cta<32)
        if((cta&3)==0){
            const int j=cta>>2;
            const float* preT=pre+(size_t)t*B*G+j*64;
            float* hout=g_d0hb[par];
            #pragma unroll
            for(int r=0;r<4;++r){
                const int b=ty*4+r;
                const float4 pv=__ldcg((const float4*)(preT+(size_t)b*G+tx*4));
                const float4 g0=__ldcg((const float4*)(g_partC0[0]+j*64+(size_t)b*G+tx*4));
                const float4 g1=__ldcg((const float4*)(g_partC0[1]+j*64+(size_t)b*G+tx*4));
                const float4 g2=__ldcg((const float4*)(g_partC0[2]+j*64+(size_t)b*G+tx*4));
                const float gi=accf(acc3[r][0],0)+pv.x+g0.x+g1.x+g2.x;
                const float gf=accf(acc3[r][0],1)+pv.y+g0.y+g1.y+g2.y;
                const float gg=accf(acc3[r][1],0)+pv.z+g0.z+g1.z+g2.z;
                const float go=accf(acc3[r][1],1)+pv.w+g0.w+g1.w+g2.w;
                const float cn=sigf(gf)*c0r[r]+sigf(gi)*tanhf(gg);
                c0r[r]=cn;
                hout[(size_t)b*H+j*16+tx]=sigf(go)*tanhf(cn);
            }
        } else if((cta&3)==1 && cta<32 && t>0){
            const int m=cta>>2;   // 0..7 (cta = 1,5,9,...,29)
            #pragma unroll
            for(int r=0;r<4;++r){
                const int b=ty*4+r;
                const float4 p0=__ldcg((const float4*)(g_partL[0]+m*64+(size_t)b*V+tx*4));
                const float4 p1=__ldcg((const float4*)(g_partL[1]+m*64+(size_t)b*V+tx*4));
                const float4 bo=*(const float4*)(bout+m*64+tx*4);
                float4 o;
                o.x=p0.x+p1.x+bo.x; o.y=p0.y+p1.y+bo.y;
                o.z=p0.z+p1.z+bo.z; o.w=p0.w+p1.w+bo.w;
                *(float4*)(out+(size_t)b*(T*V)+(size_t)(t-1)*V+m*64+tx*4)=o;
            }
        }
        gbar(ph);

        // P5: wih1 2-way K split (cta<64); kh=0 keeps regs, kh=1 stores partial
        ull acc5[4][2]={{0,0},{0,0},{0,0},{0,0}};
        if(cta<64){
            const int i2=cta>>1, kh=cta&1;
            gcoreT<128>(g_d0hb[par]+kh*256, H, g_wD1ih+(size_t)i2*64*H+kh*256, H, 256, As,Bs,acc5);
            if(kh==1) store_raw(acc5, g_partC1+i2*64, G);
        }
        gbar(ph);

        // P6: cell1 epilogue (even cta<64)
        if(cta<64 && !(cta&1)){
            const int i2=cta>>1;
            float* hout=g_d1hb[par];
            const float4 bv=*(const float4*)(g_bd1+i2*64+tx*4);
            #pragma unroll
            for(int r=0;r<4;++r){
                const int b=ty*4+r;
                const float4 p1=__ldcg((const float4*)(g_partC1+i2*64+(size_t)b*G+tx*4));
                const float4 w0=__ldcg((const float4*)(g_partW1[0]+i2*64+(size_t)b*G+tx*4));
                const float4 w1=__ldcg((const float4*)(g_partW1[1]+i2*64+(size_t)b*G+tx*4));
                const float gi=accf(acc5[r][0],0)+p1.x+w0.x+w1.x+bv.x;
                const float gf=accf(acc5[r][0],1)+p1.y+w0.y+w1.y+bv.y;
                const float gg=accf(acc5[r][1],0)+p1.z+w0.z+w1.z+bv.z;
                const float go=accf(acc5[r][1],1)+p1.w+w0.w+w1.w+bv.w;
                const float cn=sigf(gf)*c1r[r]+sigf(gi)*tanhf(gg);
                c1r[r]=cn;
                hout[(size_t)b*H+i2*16+tx]=sigf(go)*tanhf(cn);
            }
        }
        gbar(ph);
    }

    // final logits t=T-1 (d1h at parity 1): partials then finalize
    if(cta>=32&&cta<48){
        const int m=(cta-32)>>1, kh=cta&1;
        ull a1[4][2]={{0,0},{0,0},{0,0},{0,0}};
        gcoreT<128>(g_d1hb[1]+kh*256, H, Wout+(size_t)m*64*H+kh*256, H, 256, As,Bs,a1);
        store_raw(a1, g_partL[kh]+m*64, V);
    }
    gbar(ph);
    if(cta>=48&&cta<56){
        const int m=cta-48;
        #pragma unroll
        for(int r=0;r<4;++r){
            const int b=ty*4+r;
            const float4 p0=__ldcg((const float4*)(g_partL[0]+m*64+(size_t)b*V+tx*4));
            const float4 p1=__ldcg((const float4*)(g_partL[1]+m*64+(size_t)b*V+tx*4));
            const float4 bo=*(const float4*)(bout+m*64+tx*4);
            float4 o;
            o.x=p0.x+p1.x+bo.x; o.y=p0.y+p1.y+bo.y;
            o.z=p0.z+p1.z+bo.z; o.w=p0.w+p1.w+bo.w;
            *(float4*)(out+(size_t)b*(T*V)+(size_t)(T-1)*V+m*64+tx*4)=o;
        }
    }
}

static inline void* sym(const void* s){ void* p=nullptr; cudaGetSymbolAddress(&p,s); return p; }

extern "C" void kernel_launch(void* const* d_in, const int* in_sizes, int n_in,
                              void* d_out, int out_size)
{
    (void)in_sizes;(void)n_in;(void)out_size;
    const int* src=(const int*)d_in[0];
    const int* decin=(const int*)d_in[1];
    const float* emb=(const float*)d_in[2];
    const float* eWih0=(const float*)d_in[3];
    const float* eWhh0=(const float*)d_in[4];
    const float* ebih0=(const float*)d_in[5];
    const float* ebhh0=(const float*)d_in[6];
    const float* eWih1=(const float*)d_in[7];
    const float* eWhh1=(const float*)d_in[8];
    const float* ebih1=(const float*)d_in[9];
    const float* ebhh1=(const float*)d_in[10];
    const float* dWih0=(const float*)d_in[11];
    const float* dWhh0=(const float*)d_in[12];
    const float* dbih0=(const float*)d_in[13];
    const float* dbhh0=(const float*)d_in[14];
    const float* dWih1=(const float*)d_in[15];
    const float* dWhh1=(const float*)d_in[16];
    const float* dbih1=(const float*)d_in[17];
    const float* dbhh1=(const float*)d_in[18];
    const float* Wq=(const float*)d_in[19];
    const float* bq=(const float*)d_in[20];
    const float* Wout=(const float*)d_in[21];
    const float* bout=(const float*)d_in[22];
    float* out=(float*)d_out;

    float* xs=(float*)sym(g_xs);    float* pre=(float*)sym(g_pre);
    float* preD=(float*)sym(g_preD);
    float* y0=(float*)sym(g_y0);
    __nv_bfloat16* encb=(__nv_bfloat16*)sym(g_encb);
    float* edec=(float*)sym(g_edec);
    float* wE0ih=(float*)sym(g_wE0ih); float* wE0hh=(float*)sym(g_wE0hh);
    float* wE1ih=(float*)sym(g_wE1ih); float* wE1hh=(float*)sym(g_wE1hh);
    float* wD0=(float*)sym(g_wD0);
    float* be0=(float*)sym(g_be0);  float* be1=(float*)sym(g_be1);
    float* bd0=(float*)sym(g_bd0);
    float* h0i=(float*)sym(g_h0i);  float* c0i=(float*)sym(g_c0i);
    float* h1i=(float*)sym(g_h1i);  float* c1i=(float*)sym(g_c1i);

    prep_k<<<512,256>>>(src,decin,emb,
        eWih0,eWhh0,ebih0,ebhh0, eWih1,eWhh1,ebih1,ebhh1,
        dWih0,dWhh0,dbih0,dbhh0, dWih1,dWhh1,dbih1,dbhh1);

    const long long SBG=(long long)S*B*G;
    gemm2_k<<<dim3(32,(T*B)/64,1),NTG>>>(edec,E,E, wD0,EH2, bd0, preD,G, 0,0,0,0);
    gemm2_k<<<dim3(32,(S*B)/64,2),NTG>>>(xs,E,E, wE0ih,E, be0, pre,G,
        (long long)S*B*E,(long long)G*E,G,SBG);
    enc_layer_k<<<NB,NTP>>>(pre, wE0hh, y0, y0+(size_t)S*B*H2, nullptr, h0i,c0i);
    gemm2_k<<<dim3(32,(S*B)/64,2),NTG>>>(y0,H2,H2, wE1ih,H2, be1, pre,G,
        (long long)S*B*H2,(long long)G*H2,G,SBG);
    enc_layer_k<<<NB,NTP>>>(pre, wE1hh, nullptr, nullptr, encb, h1i,c1i);
    dec_k<<<NB,NTP>>>(preD, src, encb, Wq,bq, Wout,bout, out);
}